// round 8
// baseline (speedup 1.0000x reference)
#include <cuda_runtime.h>
#include <cuda_bf16.h>
#include <math.h>
#include <stdint.h>

#define BB 4
#define TT 256
#define UU 64
#define UP 65          // U+1
#define DJ 512
#define VV 1024
#define MTILE 64       // lattice rows per joint CTA
#define A_BYTES (MTILE*DJ*2)     // 65536
#define BT_BYTES (128*128)       // 16384: 128n x 64k bf16, 128B rows
#define NBUF 3
#define NTILES 64                // 8 nc x 8 ktile
#define JTHREADS 256

// ---------------- scratch ----------------
__device__ float g_enc_h[BB*TT*DJ];
__device__ float g_dec_h[BB*UP*DJ];
__device__ float g_blank[BB*TT*UP];
__device__ float g_emit [BB*TT*UU];
__device__ float g_final[BB];
__device__ __nv_bfloat16 g_wp[VV*DJ];   // W_proj bf16 [V][K] row-major

// ---------------- helpers ----------------
__device__ __forceinline__ uint32_t smem_u32(const void* p) {
    uint32_t a;
    asm("{ .reg .u64 t; cvta.to.shared.u64 t, %1; cvt.u32.u64 %0, t; }" : "=r"(a) : "l"(p));
    return a;
}
__device__ __forceinline__ float tanh_fast(float x) {
    float r; asm("tanh.approx.f32 %0, %1;" : "=f"(r) : "f"(x)); return r;
}
__device__ __forceinline__ uint32_t pack_bf16x2(float lo, float hi) {
    uint32_t r; asm("cvt.rn.bf16x2.f32 %0, %1, %2;" : "=r"(r) : "f"(hi), "f"(lo)); return r;
}
__device__ __forceinline__ void cp_async16(uint32_t dst, const void* src) {
    asm volatile("cp.async.cg.shared.global [%0], [%1], 16;\n" :: "r"(dst), "l"(src) : "memory");
}
__device__ __forceinline__ void ldsm_x4(uint32_t (&r)[4], uint32_t addr) {
    asm volatile("ldmatrix.sync.aligned.m8n8.x4.shared.b16 {%0,%1,%2,%3}, [%4];"
                 : "=r"(r[0]), "=r"(r[1]), "=r"(r[2]), "=r"(r[3]) : "r"(addr));
}
__device__ __forceinline__ void mma_bf16(float (&c)[4], const uint32_t (&a)[4],
                                         uint32_t b0, uint32_t b1) {
    asm volatile(
        "mma.sync.aligned.m16n8k16.row.col.f32.bf16.bf16.f32 "
        "{%0,%1,%2,%3}, {%4,%5,%6,%7}, {%8,%9}, {%0,%1,%2,%3};"
        : "+f"(c[0]), "+f"(c[1]), "+f"(c[2]), "+f"(c[3])
        : "r"(a[0]), "r"(a[1]), "r"(a[2]), "r"(a[3]), "r"(b0), "r"(b1));
}

// =====================================================================
// K0: W_proj fp32 -> bf16
// =====================================================================
__global__ void convert_wp_kernel(const float* __restrict__ Wp) {
    int idx = blockIdx.x * 256 + threadIdx.x;
    g_wp[idx] = __float2bfloat16(Wp[idx]);
}

// =====================================================================
// K1: both projections in one launch (z=0: enc, z=1: dec)
// =====================================================================
__global__ void __launch_bounds__(256) gemm_bias_kernel(
    const float* __restrict__ A0, const float* __restrict__ W0,
    const float* __restrict__ b0, float* __restrict__ C0, int M0,
    const float* __restrict__ A1, const float* __restrict__ W1,
    const float* __restrict__ b1, float* __restrict__ C1, int M1)
{
    const float* A; const float* W; const float* bias; float* C; int M;
    if (blockIdx.z == 0) { A = A0; W = W0; bias = b0; C = C0; M = M0; }
    else                 { A = A1; W = W1; bias = b1; C = C1; M = M1; }
    const int m0 = blockIdx.x * 64;
    if (m0 >= M) return;
    const int n0 = blockIdx.y * 64;
    const int K = 512, N = DJ;

    __shared__ float As[16][64];
    __shared__ float Ws[16][64];
    const int tid = threadIdx.x;
    const int tm = tid >> 4, tn = tid & 15;

    float acc[4][4];
#pragma unroll
    for (int i = 0; i < 4; i++)
#pragma unroll
        for (int j = 0; j < 4; j++) acc[i][j] = 0.f;

    for (int k0 = 0; k0 < K; k0 += 16) {
        __syncthreads();
#pragma unroll
        for (int i = 0; i < 4; i++) {
            int q = tid + i * 256;
            int mm = q >> 4, kk = q & 15;
            int gm = m0 + mm;
            As[kk][mm] = (gm < M) ? A[(size_t)gm * K + k0 + kk] : 0.f;
            int gn = n0 + mm;
            Ws[kk][mm] = W[(size_t)gn * K + k0 + kk];
        }
        __syncthreads();
#pragma unroll
        for (int kk = 0; kk < 16; kk++) {
            float a[4], w[4];
#pragma unroll
            for (int i = 0; i < 4; i++) a[i] = As[kk][tm * 4 + i];
#pragma unroll
            for (int j = 0; j < 4; j++) w[j] = Ws[kk][tn * 4 + j];
#pragma unroll
            for (int i = 0; i < 4; i++)
#pragma unroll
                for (int j = 0; j < 4; j++) acc[i][j] = fmaf(a[i], w[j], acc[i][j]);
        }
    }
#pragma unroll
    for (int i = 0; i < 4; i++) {
        int gm = m0 + tm * 4 + i;
        if (gm < M) {
#pragma unroll
            for (int j = 0; j < 4; j++) {
                int gn = n0 + tn * 4 + j;
                C[(size_t)gm * N + gn] = acc[i][j] + bias[gn];
            }
        }
    }
}

// =====================================================================
// K3: mma.sync bf16 joint GEMM + fused log-softmax (2 CTA/SM, NBUF=3)
// =====================================================================
__device__ __forceinline__ void load_b_tile(int bt, uint32_t b_base, int tid) {
    uint32_t buf = b_base + (uint32_t)(bt % NBUF) * BT_BYTES;
    const int nc = bt >> 3, ktl = bt & 7;
    const int n = tid >> 1;                 // 128 rows, 2 threads/row
    const int c0 = (tid & 1) * 4;           // 4 x 16B per thread
    const __nv_bfloat16* src = g_wp + ((size_t)(nc * 128 + n) * DJ + ktl * 64 + c0 * 8);
    const uint32_t row = buf + (uint32_t)n * 128u;
    const uint32_t sw = (uint32_t)(n & 7);
#pragma unroll
    for (int j = 0; j < 4; j++) {
        uint32_t c = (uint32_t)(c0 + j);
        cp_async16(row + ((c ^ sw) << 4), src + j * 8);
    }
    asm volatile("cp.async.commit_group;" ::: "memory");
}

__global__ void __launch_bounds__(JTHREADS, 2) joint_kernel(const int* __restrict__ targets)
{
    extern __shared__ __align__(16) char dyn[];
    __shared__ int tgtm[MTILE];

    const uint32_t base = (smem_u32(dyn) + 1023u) & ~1023u;
    const uint32_t a_base = base;
    const uint32_t b_base = base + A_BYTES;

    const int tid  = threadIdx.x;
    const int lane = tid & 31;
    const int wid  = tid >> 5;
    const int warp_m = wid & 1;     // 2 M-warps of 32 rows
    const int warp_n = wid >> 1;    // 4 N-warps of 32 cols (over 128-col chunk)
    const int g0 = blockIdx.x * MTILE;
    const unsigned FM = 0xffffffffu;

    if (tid < MTILE) {
        int g = g0 + tid;
        int b = g / (TT * UP);
        int r = g - b * (TT * UP);
        int u = r % UP;
        tgtm[tid] = (u < UU) ? targets[b * UU + u] : -1;
    }

    // ---- generate h tile into XOR-swizzled A (bf16); each thread 128 k ----
    {
        const int m = tid >> 2;
        const int kq = (tid & 3) * 128;
        int g = g0 + m;
        int b = g / (TT * UP);
        int r = g - b * (TT * UP);
        int t = r / UP, u = r - t * UP;
        const float4* er = reinterpret_cast<const float4*>(
            g_enc_h + ((size_t)(b * TT + t)) * DJ + kq);
        const float4* dr = reinterpret_cast<const float4*>(
            g_dec_h + ((size_t)(b * UP + u)) * DJ + kq);
        const uint32_t mrow = a_base + (uint32_t)m * 1024u;
        const uint32_t msw = (uint32_t)(m & 7);
#pragma unroll 4
        for (int i = 0; i < 16; i++) {
            int k = kq + i * 8;
            float4 e0 = er[i * 2], e1 = er[i * 2 + 1];
            float4 d0 = dr[i * 2], d1 = dr[i * 2 + 1];
            uint32_t p0 = pack_bf16x2(tanh_fast(e0.x * d0.x), tanh_fast(e0.y * d0.y));
            uint32_t p1 = pack_bf16x2(tanh_fast(e0.z * d0.z), tanh_fast(e0.w * d0.w));
            uint32_t p2 = pack_bf16x2(tanh_fast(e1.x * d1.x), tanh_fast(e1.y * d1.y));
            uint32_t p3 = pack_bf16x2(tanh_fast(e1.z * d1.z), tanh_fast(e1.w * d1.w));
            uint32_t c = (uint32_t)(k >> 3);
            uint32_t addr = mrow + ((c ^ msw) << 4);
            asm volatile("st.shared.v4.b32 [%0], {%1,%2,%3,%4};"
                         :: "r"(addr), "r"(p0), "r"(p1), "r"(p2), "r"(p3) : "memory");
        }
    }

    // ---- prologue: prefetch B tiles 0,1 ----
    load_b_tile(0, b_base, tid);
    load_b_tile(1, b_base, tid);
    __syncthreads();   // h tile visible to all warps

    // ---- per-lane ldmatrix addressing ----
    const int rowA = warp_m * 32 + (lane & 15);
    const uint32_t a_lane = a_base + (uint32_t)rowA * 1024u;
    const uint32_t swzA = (uint32_t)(rowA & 7);
    const uint32_t cbaseA = (uint32_t)(lane >> 4);
    const int n_row_base = warp_n * 32 + ((lane >> 4) << 3) + (lane & 7);
    const uint32_t kh = (uint32_t)((lane >> 3) & 1);
    const uint32_t swzB = (uint32_t)(lane & 7);
    uint32_t rowoffB[2];
#pragma unroll
    for (int p = 0; p < 2; p++) rowoffB[p] = (uint32_t)(n_row_base + p * 16) * 128u;

    // ---- per-row epilogue state ----
    float sm[4], blankv[4], tgtv[4];
    int tg[4];
#pragma unroll
    for (int g = 0; g < 4; g++) {
        sm[g] = 0.f; blankv[g] = 0.f; tgtv[g] = 0.f;
        int m = warp_m * 32 + (g >> 1) * 16 + (g & 1) * 8 + (lane >> 2);
        tg[g] = tgtm[m];
    }

    float acc[2][4][4];

#pragma unroll 1
    for (int bt = 0; bt < NTILES; bt++) {
        const int ktl = bt & 7;
        // tile bt complete for THIS thread...
        if (bt < NTILES - 1) asm volatile("cp.async.wait_group 1;" ::: "memory");
        else                 asm volatile("cp.async.wait_group 0;" ::: "memory");
        // ...and for ALL threads (also: compute of bt-1 done -> buffer (bt+2)%3 free)
        __syncthreads();
        if (bt + 2 < NTILES) load_b_tile(bt + 2, b_base, tid);

        if (ktl == 0) {
#pragma unroll
            for (int mi = 0; mi < 2; mi++)
#pragma unroll
                for (int nf = 0; nf < 4; nf++)
#pragma unroll
                    for (int j = 0; j < 4; j++) acc[mi][nf][j] = 0.f;
        }

        const uint32_t bbuf = b_base + (uint32_t)(bt % NBUF) * BT_BYTES;
#pragma unroll
        for (int s = 0; s < 4; s++) {
            uint32_t a0[4], a1[4];
            uint32_t cA = (uint32_t)(ktl * 8 + s * 2) + cbaseA;
            uint32_t aaddr = a_lane + ((cA ^ swzA) << 4);
            ldsm_x4(a0, aaddr);
            ldsm_x4(a1, aaddr + 16384u);
            uint32_t b[2][4];
            uint32_t cB = ((uint32_t)(s * 2) + kh) ^ swzB;
#pragma unroll
            for (int p = 0; p < 2; p++)
                ldsm_x4(b[p], bbuf + rowoffB[p] + (cB << 4));
#pragma unroll
            for (int p = 0; p < 2; p++) {
                mma_bf16(acc[0][2 * p],     a0, b[p][0], b[p][1]);
                mma_bf16(acc[0][2 * p + 1], a0, b[p][2], b[p][3]);
                mma_bf16(acc[1][2 * p],     a1, b[p][0], b[p][1]);
                mma_bf16(acc[1][2 * p + 1], a1, b[p][2], b[p][3]);
            }
        }

        if (ktl == 7) {
            const int nc = bt >> 3;
            const int vbase = nc * 128 + warp_n * 32 + (lane & 3) * 2;
#pragma unroll
            for (int g = 0; g < 4; g++) {
                const int mi = g >> 1, hf = (g & 1) * 2;
                float ls = 0.f;
#pragma unroll
                for (int nf = 0; nf < 4; nf++)
                    ls += __expf(acc[mi][nf][hf]) + __expf(acc[mi][nf][hf + 1]);
                ls += __shfl_xor_sync(FM, ls, 1);
                ls += __shfl_xor_sync(FM, ls, 2);
                sm[g] += ls;
#pragma unroll
                for (int nf = 0; nf < 4; nf++) {
                    int v0 = vbase + nf * 8;
                    if (v0 == 0)         blankv[g] = acc[mi][nf][hf];
                    if (v0 == tg[g])     tgtv[g]   = acc[mi][nf][hf];
                    if (v0 + 1 == tg[g]) tgtv[g]   = acc[mi][nf][hf + 1];
                }
            }
        }
    }

    // gather captured values across the 4 lanes of each row group
#pragma unroll
    for (int g = 0; g < 4; g++) {
        tgtv[g]   += __shfl_xor_sync(FM, tgtv[g], 1);
        tgtv[g]   += __shfl_xor_sync(FM, tgtv[g], 2);
        blankv[g] += __shfl_xor_sync(FM, blankv[g], 1);
        blankv[g] += __shfl_xor_sync(FM, blankv[g], 2);
    }

    // reuse B buffer smem for the cross-n-warp combine
    __syncthreads();
    float* ssum   = reinterpret_cast<float*>(dyn) + ((b_base - smem_u32(dyn)) >> 2);
    float* stgtv  = ssum + 4 * MTILE;
    float* sblank = stgtv + 4 * MTILE;

    if ((lane & 3) == 0) {
#pragma unroll
        for (int g = 0; g < 4; g++) {
            int m = warp_m * 32 + (g >> 1) * 16 + (g & 1) * 8 + (lane >> 2);
            ssum[warp_n * MTILE + m]  = sm[g];
            stgtv[warp_n * MTILE + m] = tgtv[g];
            if (warp_n == 0) sblank[m] = blankv[g];
        }
    }
    __syncthreads();

    if (tid < MTILE) {
        int m = tid;
        float lse = __logf(ssum[m] + ssum[MTILE + m] + ssum[2 * MTILE + m] + ssum[3 * MTILE + m]);
        int g = g0 + m;
        int b = g / (TT * UP);
        int r = g - b * (TT * UP);
        int t = r / UP, u = r - t * UP;
        g_blank[g] = sblank[m] - lse;
        if (u < UU) {
            int h = (tgtm[m] >> 5) & 3;   // which 32-col N-warp owns target (mod 128)
            g_emit[(size_t)(b * TT + t) * UU + u] = stgtv[h * MTILE + m] - lse;
        }
    }
}

// =====================================================================
// K4: alpha DP — fused (E,M,S) semiring scan, one warp per batch
// =====================================================================
__global__ void dp_kernel(const int* __restrict__ in_len, const int* __restrict__ tgt_len) {
    const int b = blockIdx.x;
    const int lane = threadIdx.x;
    const float* blank = g_blank + (size_t)b * TT * UP;
    const float* emit  = g_emit  + (size_t)b * TT * UU;
    const int til = in_len[b];
    const int ul  = tgt_len[b];
    const int u0 = lane * 3;
    const unsigned FM = 0xffffffffu;
    const bool a0ok = (u0 < UP), a1ok = (u0 + 1 < UP), a2ok = (u0 + 2 < UP);

    float alpha[3];

    {
        float x0 = (u0 >= 1 && a0ok) ? emit[u0 - 1] : 0.f;
        float x1 = a1ok ? emit[u0] : 0.f;
        float x2 = a2ok ? emit[u0 + 1] : 0.f;
        float s0 = x0, s1 = s0 + x1, s2 = s1 + x2;
        float tot = s2;
#pragma unroll
        for (int o = 1; o < 32; o <<= 1) {
            float n = __shfl_up_sync(FM, tot, o);
            if (lane >= o) tot += n;
        }
        float ex = __shfl_up_sync(FM, tot, 1);
        if (lane == 0) ex = 0.f;
        alpha[0] = ex + s0; alpha[1] = ex + s1; alpha[2] = ex + s2;
    }

    float bl[3], xe[3];
    {
        const float* bp = blank;
        bl[0] = a0ok ? bp[u0] : 0.f;
        bl[1] = a1ok ? bp[u0 + 1] : 0.f;
        bl[2] = a2ok ? bp[u0 + 2] : 0.f;
        const float* ep = emit + UU;
        xe[0] = (u0 >= 1 && a0ok) ? ep[u0 - 1] : 0.f;
        xe[1] = a1ok ? ep[u0] : 0.f;
        xe[2] = a2ok ? ep[u0 + 1] : 0.f;
    }

    for (int t = 1; t < til; t++) {
        float nbl[3], nxe[3];
        if (t + 1 < til) {
            const float* bp = blank + (size_t)t * UP;
            nbl[0] = a0ok ? bp[u0] : 0.f;
            nbl[1] = a1ok ? bp[u0 + 1] : 0.f;
            nbl[2] = a2ok ? bp[u0 + 2] : 0.f;
            const float* ep = emit + (size_t)(t + 1) * UU;
            nxe[0] = (u0 >= 1 && a0ok) ? ep[u0 - 1] : 0.f;
            nxe[1] = a1ok ? ep[u0] : 0.f;
            nxe[2] = a2ok ? ep[u0 + 1] : 0.f;
        }

        float tmp0 = a0ok ? (alpha[0] + bl[0]) : -1e30f;
        float tmp1 = a1ok ? (alpha[1] + bl[1]) : -1e30f;
        float tmp2 = a2ok ? (alpha[2] + bl[2]) : -1e30f;

        float E0 = xe[0], M0 = tmp0, S0 = 1.f;
        float t1 = M0 + xe[1];
        float M1 = fmaxf(t1, tmp1);
        float S1 = S0 * __expf(t1 - M1) + __expf(tmp1 - M1);
        float E1 = E0 + xe[1];
        float t2 = M1 + xe[2];
        float M2 = fmaxf(t2, tmp2);
        float S2 = S1 * __expf(t2 - M2) + __expf(tmp2 - M2);
        float E2 = E1 + xe[2];

        float Ew = E2, Mw = M2, Sw = S2;
#pragma unroll
        for (int o = 1; o < 32; o <<= 1) {
            float Ep = __shfl_up_sync(FM, Ew, o);
            float Mp = __shfl_up_sync(FM, Mw, o);
            float Sp = __shfl_up_sync(FM, Sw, o);
            if (lane >= o) {
                float tt = Mp + Ew;
                float nm = fmaxf(tt, Mw);
                Sw = Sp * __expf(tt - nm) + Sw * __expf(Mw - nm);
                Mw = nm;
                Ew = Ep + Ew;
            }
        }
        float Pe = __shfl_up_sync(FM, Ew, 1);
        float Pm = __shfl_up_sync(FM, Mw, 1);
        float Ps = __shfl_up_sync(FM, Sw, 1);
        if (lane == 0) { Pe = 0.f; Pm = -1e30f; Ps = 0.f; }

        {
            float tt = Pm + E0;
            float nm = fmaxf(tt, M0);
            float S = Ps * __expf(tt - nm) + S0 * __expf(M0 - nm);
            alpha[0] = nm + __logf(S);
        }
        {
            float tt = Pm + E1;
            float nm = fmaxf(tt, M1);
            float S = Ps * __expf(tt - nm) + S1 * __expf(M1 - nm);
            alpha[1] = nm + __logf(S);
        }
        {
            float tt = Pm + E2;
            float nm = fmaxf(tt, M2);
            float S = Ps * __expf(tt - nm) + S2 * __expf(M2 - nm);
            alpha[2] = nm + __logf(S);
        }

        bl[0] = nbl[0]; bl[1] = nbl[1]; bl[2] = nbl[2];
        xe[0] = nxe[0]; xe[1] = nxe[1]; xe[2] = nxe[2];
    }

    int j = ul - u0;
    if (j >= 0 && j < 3) {
        float a = (j == 0) ? alpha[0] : (j == 1) ? alpha[1] : alpha[2];
        g_final[b] = a + blank[(size_t)(til - 1) * UP + ul];
    }
}

__global__ void finalize_kernel(float* out) {
    out[0] = -0.25f * (g_final[0] + g_final[1] + g_final[2] + g_final[3]);
}

// =====================================================================
// launch
// =====================================================================
extern "C" void kernel_launch(void* const* d_in, const int* in_sizes, int n_in,
                              void* d_out, int out_size)
{
    const float* enc     = (const float*)d_in[0];
    const float* dec     = (const float*)d_in[1];
    const int*   targets = (const int*)  d_in[2];
    const int*   in_len  = (const int*)  d_in[3];
    const int*   tgt_len = (const int*)  d_in[4];
    const float* W_enc   = (const float*)d_in[5];
    const float* b_enc   = (const float*)d_in[6];
    const float* W_dec   = (const float*)d_in[7];
    const float* b_dec   = (const float*)d_in[8];
    const float* W_proj  = (const float*)d_in[9];

    void *pe = nullptr, *pd = nullptr;
    cudaGetSymbolAddress(&pe, g_enc_h);
    cudaGetSymbolAddress(&pd, g_dec_h);

    const int smem_joint = 1024 + A_BYTES + NBUF * BT_BYTES;   // 115712 B -> 2 CTA/SM
    cudaFuncSetAttribute(joint_kernel, cudaFuncAttributeMaxDynamicSharedMemorySize, smem_joint);

    convert_wp_kernel<<<(VV * DJ) / 256, 256>>>(W_proj);

    dim3 gg((BB * TT + 63) / 64, DJ / 64, 2);
    gemm_bias_kernel<<<gg, 256>>>(enc, W_enc, b_enc, (float*)pe, BB * TT,
                                  dec, W_dec, b_dec, (float*)pd, BB * UP);

    joint_kernel<<<(BB * TT * UP) / MTILE, JTHREADS, smem_joint>>>(targets);

    dp_kernel<<<BB, 32>>>(in_len, tgt_len);

    finalize_kernel<<<1, 1>>>((float*)d_out);
}

// round 10
// speedup vs baseline: 1.4070x; 1.4070x over previous
#include <cuda_runtime.h>
#include <cuda_bf16.h>
#include <math.h>
#include <stdint.h>

#define BB 4
#define TT 256
#define UU 64
#define UP 65          // U+1
#define DJ 512
#define VV 1024
#define MTILE 128      // lattice rows per joint CTA
#define A_BYTES (MTILE*DJ*2)     // 131072
#define BT_BYTES (256*128)       // 32768: 256n x 64k bf16, 128B rows (SW128 atom)
#define NBUF 3
#define NTILES 32                // 4 nc x 8 ktile
#define JTHREADS 512

// ---------------- scratch ----------------
__device__ float g_enc_h[BB*TT*DJ];
__device__ float g_dec_h[BB*UP*DJ];
__device__ float g_blank[BB*TT*UP];
__device__ float g_emit [BB*TT*UU];
__device__ float g_final[BB];
__device__ __nv_bfloat16 g_wp[VV*DJ];   // W_proj bf16 [V][K] row-major

// ---------------- helpers ----------------
__device__ __forceinline__ uint32_t smem_u32(const void* p) {
    uint32_t a;
    asm("{ .reg .u64 t; cvta.to.shared.u64 t, %1; cvt.u32.u64 %0, t; }" : "=r"(a) : "l"(p));
    return a;
}
__device__ __forceinline__ float tanh_fast(float x) {
    float r; asm("tanh.approx.f32 %0, %1;" : "=f"(r) : "f"(x)); return r;
}
__device__ __forceinline__ uint32_t pack_bf16x2(float lo, float hi) {
    uint32_t r; asm("cvt.rn.bf16x2.f32 %0, %1, %2;" : "=r"(r) : "f"(hi), "f"(lo)); return r;
}
__device__ __forceinline__ void cp_async16(uint32_t dst, const void* src) {
    asm volatile("cp.async.cg.shared.global [%0], [%1], 16;\n" :: "r"(dst), "l"(src) : "memory");
}
__device__ __forceinline__ void ldsm_x4(uint32_t (&r)[4], uint32_t addr) {
    asm volatile("ldmatrix.sync.aligned.m8n8.x4.shared.b16 {%0,%1,%2,%3}, [%4];"
                 : "=r"(r[0]), "=r"(r[1]), "=r"(r[2]), "=r"(r[3]) : "r"(addr));
}
__device__ __forceinline__ void mma_bf16(float (&c)[4], const uint32_t (&a)[4],
                                         uint32_t b0, uint32_t b1) {
    asm volatile(
        "mma.sync.aligned.m16n8k16.row.col.f32.bf16.bf16.f32 "
        "{%0,%1,%2,%3}, {%4,%5,%6,%7}, {%8,%9}, {%0,%1,%2,%3};"
        : "+f"(c[0]), "+f"(c[1]), "+f"(c[2]), "+f"(c[3])
        : "r"(a[0]), "r"(a[1]), "r"(a[2]), "r"(a[3]), "r"(b0), "r"(b1));
}

// =====================================================================
// K0: W_proj fp32 -> bf16
// =====================================================================
__global__ void convert_wp_kernel(const float* __restrict__ Wp) {
    int idx = blockIdx.x * 256 + threadIdx.x;
    g_wp[idx] = __float2bfloat16(Wp[idx]);
}

// =====================================================================
// K1: both projections in one launch (z=0: enc, z=1: dec)
// =====================================================================
__global__ void __launch_bounds__(256) gemm_bias_kernel(
    const float* __restrict__ A0, const float* __restrict__ W0,
    const float* __restrict__ b0, float* __restrict__ C0, int M0,
    const float* __restrict__ A1, const float* __restrict__ W1,
    const float* __restrict__ b1, float* __restrict__ C1, int M1)
{
    const float* A; const float* W; const float* bias; float* C; int M;
    if (blockIdx.z == 0) { A = A0; W = W0; bias = b0; C = C0; M = M0; }
    else                 { A = A1; W = W1; bias = b1; C = C1; M = M1; }
    const int m0 = blockIdx.x * 64;
    if (m0 >= M) return;
    const int n0 = blockIdx.y * 64;
    const int K = 512, N = DJ;

    __shared__ float As[16][64];
    __shared__ float Ws[16][64];
    const int tid = threadIdx.x;
    const int tm = tid >> 4, tn = tid & 15;

    float acc[4][4];
#pragma unroll
    for (int i = 0; i < 4; i++)
#pragma unroll
        for (int j = 0; j < 4; j++) acc[i][j] = 0.f;

    for (int k0 = 0; k0 < K; k0 += 16) {
        __syncthreads();
#pragma unroll
        for (int i = 0; i < 4; i++) {
            int q = tid + i * 256;
            int mm = q >> 4, kk = q & 15;
            int gm = m0 + mm;
            As[kk][mm] = (gm < M) ? A[(size_t)gm * K + k0 + kk] : 0.f;
            int gn = n0 + mm;
            Ws[kk][mm] = W[(size_t)gn * K + k0 + kk];
        }
        __syncthreads();
#pragma unroll
        for (int kk = 0; kk < 16; kk++) {
            float a[4], w[4];
#pragma unroll
            for (int i = 0; i < 4; i++) a[i] = As[kk][tm * 4 + i];
#pragma unroll
            for (int j = 0; j < 4; j++) w[j] = Ws[kk][tn * 4 + j];
#pragma unroll
            for (int i = 0; i < 4; i++)
#pragma unroll
                for (int j = 0; j < 4; j++) acc[i][j] = fmaf(a[i], w[j], acc[i][j]);
        }
    }
#pragma unroll
    for (int i = 0; i < 4; i++) {
        int gm = m0 + tm * 4 + i;
        if (gm < M) {
#pragma unroll
            for (int j = 0; j < 4; j++) {
                int gn = n0 + tn * 4 + j;
                C[(size_t)gm * N + gn] = acc[i][j] + bias[gn];
            }
        }
    }
}

// =====================================================================
// K3: mma.sync bf16 joint GEMM + fused log-softmax (R6 config)
// =====================================================================
__device__ __forceinline__ void load_b_tile(int bt, uint32_t b_base, int tid) {
    uint32_t buf = b_base + (uint32_t)(bt % NBUF) * BT_BYTES;
    const int nc = bt >> 3, ktl = bt & 7;
    const int n = tid >> 1;                 // 256 rows, 2 threads/row
    const int c0 = (tid & 1) * 4;           // 4 x 16B per thread
    const __nv_bfloat16* src = g_wp + ((size_t)(nc * 256 + n) * DJ + ktl * 64 + c0 * 8);
    const uint32_t row = buf + (uint32_t)n * 128u;
    const uint32_t sw = (uint32_t)(n & 7);
#pragma unroll
    for (int j = 0; j < 4; j++) {
        uint32_t c = (uint32_t)(c0 + j);
        cp_async16(row + ((c ^ sw) << 4), src + j * 8);
    }
    asm volatile("cp.async.commit_group;" ::: "memory");
}

__global__ void __launch_bounds__(JTHREADS, 1) joint_kernel(const int* __restrict__ targets)
{
    extern __shared__ __align__(16) char dyn[];
    __shared__ int tgtm[MTILE];

    const uint32_t base = (smem_u32(dyn) + 1023u) & ~1023u;
    const uint32_t a_base = base;
    const uint32_t b_base = base + A_BYTES;

    const int tid  = threadIdx.x;
    const int lane = tid & 31;
    const int wid  = tid >> 5;
    const int warp_m = wid & 3;     // 4 M-warps of 32 rows
    const int warp_n = wid >> 2;    // 4 N-warps of 64 cols (over 256-col chunk)
    const int g0 = blockIdx.x * MTILE;
    const unsigned FM = 0xffffffffu;

    if (tid < MTILE) {
        int g = g0 + tid;
        int b = g / (TT * UP);
        int r = g - b * (TT * UP);
        int u = r % UP;
        tgtm[tid] = (u < UU) ? targets[b * UU + u] : -1;
    }

    // ---- generate h tile into XOR-swizzled A (bf16); each thread 128 k ----
    {
        const int m = tid >> 2;
        const int kq = (tid & 3) * 128;
        int g = g0 + m;
        int b = g / (TT * UP);
        int r = g - b * (TT * UP);
        int t = r / UP, u = r - t * UP;
        const float4* er = reinterpret_cast<const float4*>(
            g_enc_h + ((size_t)(b * TT + t)) * DJ + kq);
        const float4* dr = reinterpret_cast<const float4*>(
            g_dec_h + ((size_t)(b * UP + u)) * DJ + kq);
        const uint32_t mrow = a_base + (uint32_t)m * 1024u;
        const uint32_t msw = (uint32_t)(m & 7);
#pragma unroll 4
        for (int i = 0; i < 16; i++) {
            int k = kq + i * 8;
            float4 e0 = er[i * 2], e1 = er[i * 2 + 1];
            float4 d0 = dr[i * 2], d1 = dr[i * 2 + 1];
            uint32_t p0 = pack_bf16x2(tanh_fast(e0.x * d0.x), tanh_fast(e0.y * d0.y));
            uint32_t p1 = pack_bf16x2(tanh_fast(e0.z * d0.z), tanh_fast(e0.w * d0.w));
            uint32_t p2 = pack_bf16x2(tanh_fast(e1.x * d1.x), tanh_fast(e1.y * d1.y));
            uint32_t p3 = pack_bf16x2(tanh_fast(e1.z * d1.z), tanh_fast(e1.w * d1.w));
            uint32_t c = (uint32_t)(k >> 3);
            uint32_t addr = mrow + ((c ^ msw) << 4);
            asm volatile("st.shared.v4.b32 [%0], {%1,%2,%3,%4};"
                         :: "r"(addr), "r"(p0), "r"(p1), "r"(p2), "r"(p3) : "memory");
        }
    }
    __syncthreads();

    // ---- prologue: prefetch B tiles 0,1 ----
    load_b_tile(0, b_base, tid);
    load_b_tile(1, b_base, tid);

    // ---- per-lane ldmatrix addressing ----
    const int rowA = warp_m * 32 + (lane & 15);
    const uint32_t a_lane = a_base + (uint32_t)rowA * 1024u;
    const uint32_t swzA = (uint32_t)(rowA & 7);
    const uint32_t cbaseA = (uint32_t)(lane >> 4);
    const int n_row_base = warp_n * 64 + ((lane >> 4) << 3) + (lane & 7);
    const uint32_t kh = (uint32_t)((lane >> 3) & 1);
    const uint32_t swzB = (uint32_t)(lane & 7);
    uint32_t rowoffB[4];
#pragma unroll
    for (int p = 0; p < 4; p++) rowoffB[p] = (uint32_t)(n_row_base + p * 16) * 128u;

    // ---- per-row epilogue state ----
    float sm[4], blankv[4], tgtv[4];
    int tg[4];
#pragma unroll
    for (int g = 0; g < 4; g++) {
        sm[g] = 0.f; blankv[g] = 0.f; tgtv[g] = 0.f;
        int m = warp_m * 32 + (g >> 1) * 16 + (g & 1) * 8 + (lane >> 2);
        tg[g] = tgtm[m];
    }

    float acc[2][8][4];

#pragma unroll 1
    for (int bt = 0; bt < NTILES; bt++) {
        const int ktl = bt & 7;
        if (bt < NTILES - 1) asm volatile("cp.async.wait_group 1;" ::: "memory");
        else                 asm volatile("cp.async.wait_group 0;" ::: "memory");
        __syncthreads();
        if (bt + 2 < NTILES) load_b_tile(bt + 2, b_base, tid);

        if (ktl == 0) {
#pragma unroll
            for (int mi = 0; mi < 2; mi++)
#pragma unroll
                for (int nf = 0; nf < 8; nf++)
#pragma unroll
                    for (int j = 0; j < 4; j++) acc[mi][nf][j] = 0.f;
        }

        const uint32_t bbuf = b_base + (uint32_t)(bt % NBUF) * BT_BYTES;
#pragma unroll
        for (int s = 0; s < 4; s++) {
            uint32_t a0[4], a1[4];
            uint32_t cA = (uint32_t)(ktl * 8 + s * 2) + cbaseA;
            uint32_t aaddr = a_lane + ((cA ^ swzA) << 4);
            ldsm_x4(a0, aaddr);
            ldsm_x4(a1, aaddr + 16384u);
            uint32_t b[4][4];
            uint32_t cB = ((uint32_t)(s * 2) + kh) ^ swzB;
#pragma unroll
            for (int p = 0; p < 4; p++)
                ldsm_x4(b[p], bbuf + rowoffB[p] + (cB << 4));
#pragma unroll
            for (int p = 0; p < 4; p++) {
                mma_bf16(acc[0][2 * p],     a0, b[p][0], b[p][1]);
                mma_bf16(acc[0][2 * p + 1], a0, b[p][2], b[p][3]);
                mma_bf16(acc[1][2 * p],     a1, b[p][0], b[p][1]);
                mma_bf16(acc[1][2 * p + 1], a1, b[p][2], b[p][3]);
            }
        }

        if (ktl == 7) {
            const int nc = bt >> 3;
            const int vbase = nc * 256 + warp_n * 64 + (lane & 3) * 2;
#pragma unroll
            for (int g = 0; g < 4; g++) {
                const int mi = g >> 1, hf = (g & 1) * 2;
                float ls = 0.f;
#pragma unroll
                for (int nf = 0; nf < 8; nf++)
                    ls += __expf(acc[mi][nf][hf]) + __expf(acc[mi][nf][hf + 1]);
                ls += __shfl_xor_sync(FM, ls, 1);
                ls += __shfl_xor_sync(FM, ls, 2);
                sm[g] += ls;
#pragma unroll
                for (int nf = 0; nf < 8; nf++) {
                    int v0 = vbase + nf * 8;
                    if (v0 == 0)         blankv[g] = acc[mi][nf][hf];
                    if (v0 == tg[g])     tgtv[g]   = acc[mi][nf][hf];
                    if (v0 + 1 == tg[g]) tgtv[g]   = acc[mi][nf][hf + 1];
                }
            }
        }
    }

    // gather captured values across the 4 lanes of each row group
#pragma unroll
    for (int g = 0; g < 4; g++) {
        tgtv[g]   += __shfl_xor_sync(FM, tgtv[g], 1);
        tgtv[g]   += __shfl_xor_sync(FM, tgtv[g], 2);
        blankv[g] += __shfl_xor_sync(FM, blankv[g], 1);
        blankv[g] += __shfl_xor_sync(FM, blankv[g], 2);
    }

    // reuse B buffer smem for the cross-n-warp combine
    __syncthreads();
    float* ssum   = reinterpret_cast<float*>(dyn) + ((b_base - smem_u32(dyn)) >> 2);
    float* stgtv  = ssum + 4 * MTILE;
    float* sblank = stgtv + 4 * MTILE;

    if ((lane & 3) == 0) {
#pragma unroll
        for (int g = 0; g < 4; g++) {
            int m = warp_m * 32 + (g >> 1) * 16 + (g & 1) * 8 + (lane >> 2);
            ssum[warp_n * MTILE + m]  = sm[g];
            stgtv[warp_n * MTILE + m] = tgtv[g];
            if (warp_n == 0) sblank[m] = blankv[g];
        }
    }
    __syncthreads();

    if (tid < MTILE) {
        int m = tid;
        float lse = __logf(ssum[m] + ssum[MTILE + m] + ssum[2 * MTILE + m] + ssum[3 * MTILE + m]);
        int g = g0 + m;
        int b = g / (TT * UP);
        int r = g - b * (TT * UP);
        int t = r / UP, u = r - t * UP;
        g_blank[g] = sblank[m] - lse;
        if (u < UU) {
            int h = (tgtm[m] >> 6) & 3;   // which 64-col N-warp owns target
            g_emit[(size_t)(b * TT + t) * UU + u] = stgtv[h * MTILE + m] - lse;
        }
    }
}

// =====================================================================
// K4: alpha DP — anti-diagonal wavefront, one warp per batch, 3 u/lane
// alpha[t,u] = LSE(alpha[t-1,u]+blank[t-1,u], alpha[t,u-1]+emit[t,u-1])
// diagonal d: cells (d-u, u); both predecessors live on diagonal d-1.
// =====================================================================
__device__ __forceinline__ float lse2(float a, float b) {
    float m = fmaxf(a, b);
    float n = fminf(a, b);
    return m + __logf(1.f + __expf(n - m));
}

__global__ void dp_kernel(const int* __restrict__ in_len, const int* __restrict__ tgt_len) {
    const int b = blockIdx.x;
    const int lane = threadIdx.x;
    const float* __restrict__ blank = g_blank + (size_t)b * TT * UP;
    const float* __restrict__ emit  = g_emit  + (size_t)b * TT * UU;
    const int til = in_len[b];
    const int ul  = tgt_len[b];
    const int dmax = til - 1 + ul;
    const float NEG = -1e30f;
    const unsigned FM = 0xffffffffu;

    int u[3];
    float al[3];
    bool uok[3];
#pragma unroll
    for (int j = 0; j < 3; j++) {
        u[j] = lane * 3 + j;
        uok[j] = (u[j] <= UU);           // u in [0,64]
        al[j] = (u[j] == 0) ? 0.f : NEG; // diagonal d=0: only (0,0)=0
    }

    // loads for step d_new: blank[(t-1)*UP + u], emit[t*UU + u-1], t = d_new - u
    float bl[3], em[3];
#pragma unroll
    for (int j = 0; j < 3; j++) {
        int t = 1 - u[j];
        bl[j] = (t >= 1 && uok[j]) ? blank[(t - 1) * UP + u[j]] : 0.f;   // t<=TT guaranteed at d=1
        em[j] = (t >= 0 && u[j] >= 1 && uok[j]) ? emit[t * UU + u[j] - 1] : 0.f;
    }

    float fin = NEG;

#pragma unroll 1
    for (int d = 1; d <= dmax; d++) {
        // prefetch next step's operands (addresses independent of alpha)
        float nbl[3], nem[3];
        if (d < dmax) {
#pragma unroll
            for (int j = 0; j < 3; j++) {
                int t = d + 1 - u[j];
                nbl[j] = (t >= 1 && t <= TT && uok[j]) ? blank[(t - 1) * UP + u[j]] : 0.f;
                nem[j] = (t >= 0 && t < TT && u[j] >= 1 && uok[j]) ? emit[t * UU + u[j] - 1] : 0.f;
            }
        }

        // neighbor alpha(t, u-1): old value from u-1 slot
        float nb0 = __shfl_up_sync(FM, al[2], 1);
        if (lane == 0) nb0 = NEG;   // u[0]==0 has no emit predecessor

        float nw[3];
        {
            float x = al[0] + bl[0];
            float y = nb0   + em[0];
            nw[0] = lse2(x, y);
        }
        {
            float x = al[1] + bl[1];
            float y = al[0] + em[1];
            nw[1] = lse2(x, y);
        }
        {
            float x = al[2] + bl[2];
            float y = al[1] + em[2];
            nw[2] = lse2(x, y);
        }

        // validity mask: cell (t,u) with t = d-u must be in [0,TT-1], u<=64
#pragma unroll
        for (int j = 0; j < 3; j++) {
            int t = d - u[j];
            if (t < 0 || t >= TT || !uok[j]) nw[j] = NEG;
            al[j] = nw[j];
            if (d == dmax && u[j] == ul) fin = nw[j];
        }

        bl[0] = nbl[0]; bl[1] = nbl[1]; bl[2] = nbl[2];
        em[0] = nem[0]; em[1] = nem[1]; em[2] = nem[2];
    }

#pragma unroll
    for (int j = 0; j < 3; j++) {
        if (u[j] == ul) g_final[b] = fin + blank[(size_t)(til - 1) * UP + ul];
    }
}

__global__ void finalize_kernel(float* out) {
    out[0] = -0.25f * (g_final[0] + g_final[1] + g_final[2] + g_final[3]);
}

// =====================================================================
// launch
// =====================================================================
extern "C" void kernel_launch(void* const* d_in, const int* in_sizes, int n_in,
                              void* d_out, int out_size)
{
    const float* enc     = (const float*)d_in[0];
    const float* dec     = (const float*)d_in[1];
    const int*   targets = (const int*)  d_in[2];
    const int*   in_len  = (const int*)  d_in[3];
    const int*   tgt_len = (const int*)  d_in[4];
    const float* W_enc   = (const float*)d_in[5];
    const float* b_enc   = (const float*)d_in[6];
    const float* W_dec   = (const float*)d_in[7];
    const float* b_dec   = (const float*)d_in[8];
    const float* W_proj  = (const float*)d_in[9];

    void *pe = nullptr, *pd = nullptr;
    cudaGetSymbolAddress(&pe, g_enc_h);
    cudaGetSymbolAddress(&pd, g_dec_h);

    const int smem_joint = 1024 + A_BYTES + NBUF * BT_BYTES;   // 230400 B
    cudaFuncSetAttribute(joint_kernel, cudaFuncAttributeMaxDynamicSharedMemorySize, smem_joint);

    convert_wp_kernel<<<(VV * DJ) / 256, 256>>>(W_proj);

    dim3 gg((BB * TT + 63) / 64, DJ / 64, 2);
    gemm_bias_kernel<<<gg, 256>>>(enc, W_enc, b_enc, (float*)pe, BB * TT,
                                  dec, W_dec, b_dec, (float*)pd, BB * UP);

    joint_kernel<<<(BB * TT * UP) / MTILE, JTHREADS, smem_joint>>>(targets);

    dp_kernel<<<BB, 32>>>(in_len, tgt_len);

    finalize_kernel<<<1, 1>>>((float*)d_out);
}

// round 11
// speedup vs baseline: 1.4898x; 1.0589x over previous
#include <cuda_runtime.h>
#include <cuda_bf16.h>
#include <math.h>
#include <stdint.h>

#define BB 4
#define TT 256
#define UU 64
#define UP 65          // U+1
#define DJ 512
#define VV 1024
#define MTILE 128      // lattice rows per joint CTA
#define A_BYTES (MTILE*DJ*2)     // 131072
#define BT_BYTES (256*128)       // 32768: 256n x 64k bf16, 128B rows (SW128 atom)
#define NBUF 3
#define NTILES 32                // 4 nc x 8 ktile
#define JTHREADS 512

// ---------------- scratch ----------------
__device__ float g_enc_h[BB*TT*DJ];
__device__ float g_dec_h[BB*UP*DJ];
__device__ float g_blank[BB*TT*UP];
__device__ float g_emit [BB*TT*UU];
__device__ float g_final[BB];
__device__ __nv_bfloat16 g_wp[VV*DJ];   // W_proj bf16 [V][K] row-major

// ---------------- helpers ----------------
__device__ __forceinline__ uint32_t smem_u32(const void* p) {
    uint32_t a;
    asm("{ .reg .u64 t; cvta.to.shared.u64 t, %1; cvt.u32.u64 %0, t; }" : "=r"(a) : "l"(p));
    return a;
}
__device__ __forceinline__ float tanh_fast(float x) {
    float r; asm("tanh.approx.f32 %0, %1;" : "=f"(r) : "f"(x)); return r;
}
__device__ __forceinline__ uint32_t pack_bf16x2(float lo, float hi) {
    uint32_t r; asm("cvt.rn.bf16x2.f32 %0, %1, %2;" : "=r"(r) : "f"(hi), "f"(lo)); return r;
}
__device__ __forceinline__ void cp_async16(uint32_t dst, const void* src) {
    asm volatile("cp.async.cg.shared.global [%0], [%1], 16;\n" :: "r"(dst), "l"(src) : "memory");
}
__device__ __forceinline__ void ldsm_x4(uint32_t (&r)[4], uint32_t addr) {
    asm volatile("ldmatrix.sync.aligned.m8n8.x4.shared.b16 {%0,%1,%2,%3}, [%4];"
                 : "=r"(r[0]), "=r"(r[1]), "=r"(r[2]), "=r"(r[3]) : "r"(addr));
}
__device__ __forceinline__ void mma_bf16(float (&c)[4], const uint32_t (&a)[4],
                                         uint32_t b0, uint32_t b1) {
    asm volatile(
        "mma.sync.aligned.m16n8k16.row.col.f32.bf16.bf16.f32 "
        "{%0,%1,%2,%3}, {%4,%5,%6,%7}, {%8,%9}, {%0,%1,%2,%3};"
        : "+f"(c[0]), "+f"(c[1]), "+f"(c[2]), "+f"(c[3])
        : "r"(a[0]), "r"(a[1]), "r"(a[2]), "r"(a[3]), "r"(b0), "r"(b1));
}

// =====================================================================
// K0: W_proj fp32 -> bf16
// =====================================================================
__global__ void convert_wp_kernel(const float* __restrict__ Wp) {
    int idx = blockIdx.x * 256 + threadIdx.x;
    g_wp[idx] = __float2bfloat16(Wp[idx]);
}

// =====================================================================
// K1: both projections in one launch (z=0: enc, z=1: dec)
// =====================================================================
__global__ void __launch_bounds__(256) gemm_bias_kernel(
    const float* __restrict__ A0, const float* __restrict__ W0,
    const float* __restrict__ b0, float* __restrict__ C0, int M0,
    const float* __restrict__ A1, const float* __restrict__ W1,
    const float* __restrict__ b1, float* __restrict__ C1, int M1)
{
    const float* A; const float* W; const float* bias; float* C; int M;
    if (blockIdx.z == 0) { A = A0; W = W0; bias = b0; C = C0; M = M0; }
    else                 { A = A1; W = W1; bias = b1; C = C1; M = M1; }
    const int m0 = blockIdx.x * 64;
    if (m0 >= M) return;
    const int n0 = blockIdx.y * 64;
    const int K = 512, N = DJ;

    __shared__ float As[16][64];
    __shared__ float Ws[16][64];
    const int tid = threadIdx.x;
    const int tm = tid >> 4, tn = tid & 15;

    float acc[4][4];
#pragma unroll
    for (int i = 0; i < 4; i++)
#pragma unroll
        for (int j = 0; j < 4; j++) acc[i][j] = 0.f;

    for (int k0 = 0; k0 < K; k0 += 16) {
        __syncthreads();
#pragma unroll
        for (int i = 0; i < 4; i++) {
            int q = tid + i * 256;
            int mm = q >> 4, kk = q & 15;
            int gm = m0 + mm;
            As[kk][mm] = (gm < M) ? A[(size_t)gm * K + k0 + kk] : 0.f;
            int gn = n0 + mm;
            Ws[kk][mm] = W[(size_t)gn * K + k0 + kk];
        }
        __syncthreads();
#pragma unroll
        for (int kk = 0; kk < 16; kk++) {
            float a[4], w[4];
#pragma unroll
            for (int i = 0; i < 4; i++) a[i] = As[kk][tm * 4 + i];
#pragma unroll
            for (int j = 0; j < 4; j++) w[j] = Ws[kk][tn * 4 + j];
#pragma unroll
            for (int i = 0; i < 4; i++)
#pragma unroll
                for (int j = 0; j < 4; j++) acc[i][j] = fmaf(a[i], w[j], acc[i][j]);
        }
    }
#pragma unroll
    for (int i = 0; i < 4; i++) {
        int gm = m0 + tm * 4 + i;
        if (gm < M) {
#pragma unroll
            for (int j = 0; j < 4; j++) {
                int gn = n0 + tn * 4 + j;
                C[(size_t)gm * N + gn] = acc[i][j] + bias[gn];
            }
        }
    }
}

// =====================================================================
// K3: mma.sync bf16 joint GEMM + fused log-softmax (R6 config)
// =====================================================================
__device__ __forceinline__ void load_b_tile(int bt, uint32_t b_base, int tid) {
    uint32_t buf = b_base + (uint32_t)(bt % NBUF) * BT_BYTES;
    const int nc = bt >> 3, ktl = bt & 7;
    const int n = tid >> 1;                 // 256 rows, 2 threads/row
    const int c0 = (tid & 1) * 4;           // 4 x 16B per thread
    const __nv_bfloat16* src = g_wp + ((size_t)(nc * 256 + n) * DJ + ktl * 64 + c0 * 8);
    const uint32_t row = buf + (uint32_t)n * 128u;
    const uint32_t sw = (uint32_t)(n & 7);
#pragma unroll
    for (int j = 0; j < 4; j++) {
        uint32_t c = (uint32_t)(c0 + j);
        cp_async16(row + ((c ^ sw) << 4), src + j * 8);
    }
    asm volatile("cp.async.commit_group;" ::: "memory");
}

__global__ void __launch_bounds__(JTHREADS, 1) joint_kernel(const int* __restrict__ targets)
{
    extern __shared__ __align__(16) char dyn[];
    __shared__ int tgtm[MTILE];

    const uint32_t base = (smem_u32(dyn) + 1023u) & ~1023u;
    const uint32_t a_base = base;
    const uint32_t b_base = base + A_BYTES;

    const int tid  = threadIdx.x;
    const int lane = tid & 31;
    const int wid  = tid >> 5;
    const int warp_m = wid & 3;     // 4 M-warps of 32 rows
    const int warp_n = wid >> 2;    // 4 N-warps of 64 cols (over 256-col chunk)
    const int g0 = blockIdx.x * MTILE;
    const unsigned FM = 0xffffffffu;

    if (tid < MTILE) {
        int g = g0 + tid;
        int b = g / (TT * UP);
        int r = g - b * (TT * UP);
        int u = r % UP;
        tgtm[tid] = (u < UU) ? targets[b * UU + u] : -1;
    }

    // ---- generate h tile into XOR-swizzled A (bf16); each thread 128 k ----
    {
        const int m = tid >> 2;
        const int kq = (tid & 3) * 128;
        int g = g0 + m;
        int b = g / (TT * UP);
        int r = g - b * (TT * UP);
        int t = r / UP, u = r - t * UP;
        const float4* er = reinterpret_cast<const float4*>(
            g_enc_h + ((size_t)(b * TT + t)) * DJ + kq);
        const float4* dr = reinterpret_cast<const float4*>(
            g_dec_h + ((size_t)(b * UP + u)) * DJ + kq);
        const uint32_t mrow = a_base + (uint32_t)m * 1024u;
        const uint32_t msw = (uint32_t)(m & 7);
#pragma unroll 4
        for (int i = 0; i < 16; i++) {
            int k = kq + i * 8;
            float4 e0 = er[i * 2], e1 = er[i * 2 + 1];
            float4 d0 = dr[i * 2], d1 = dr[i * 2 + 1];
            uint32_t p0 = pack_bf16x2(tanh_fast(e0.x * d0.x), tanh_fast(e0.y * d0.y));
            uint32_t p1 = pack_bf16x2(tanh_fast(e0.z * d0.z), tanh_fast(e0.w * d0.w));
            uint32_t p2 = pack_bf16x2(tanh_fast(e1.x * d1.x), tanh_fast(e1.y * d1.y));
            uint32_t p3 = pack_bf16x2(tanh_fast(e1.z * d1.z), tanh_fast(e1.w * d1.w));
            uint32_t c = (uint32_t)(k >> 3);
            uint32_t addr = mrow + ((c ^ msw) << 4);
            asm volatile("st.shared.v4.b32 [%0], {%1,%2,%3,%4};"
                         :: "r"(addr), "r"(p0), "r"(p1), "r"(p2), "r"(p3) : "memory");
        }
    }
    __syncthreads();

    // ---- prologue: prefetch B tiles 0,1 ----
    load_b_tile(0, b_base, tid);
    load_b_tile(1, b_base, tid);

    // ---- per-lane ldmatrix addressing ----
    const int rowA = warp_m * 32 + (lane & 15);
    const uint32_t a_lane = a_base + (uint32_t)rowA * 1024u;
    const uint32_t swzA = (uint32_t)(rowA & 7);
    const uint32_t cbaseA = (uint32_t)(lane >> 4);
    const int n_row_base = warp_n * 64 + ((lane >> 4) << 3) + (lane & 7);
    const uint32_t kh = (uint32_t)((lane >> 3) & 1);
    const uint32_t swzB = (uint32_t)(lane & 7);
    uint32_t rowoffB[4];
#pragma unroll
    for (int p = 0; p < 4; p++) rowoffB[p] = (uint32_t)(n_row_base + p * 16) * 128u;

    // ---- per-row epilogue state ----
    float sm[4], blankv[4], tgtv[4];
    int tg[4];
#pragma unroll
    for (int g = 0; g < 4; g++) {
        sm[g] = 0.f; blankv[g] = 0.f; tgtv[g] = 0.f;
        int m = warp_m * 32 + (g >> 1) * 16 + (g & 1) * 8 + (lane >> 2);
        tg[g] = tgtm[m];
    }

    float acc[2][8][4];

#pragma unroll 1
    for (int bt = 0; bt < NTILES; bt++) {
        const int ktl = bt & 7;
        if (bt < NTILES - 1) asm volatile("cp.async.wait_group 1;" ::: "memory");
        else                 asm volatile("cp.async.wait_group 0;" ::: "memory");
        __syncthreads();
        if (bt + 2 < NTILES) load_b_tile(bt + 2, b_base, tid);

        if (ktl == 0) {
#pragma unroll
            for (int mi = 0; mi < 2; mi++)
#pragma unroll
                for (int nf = 0; nf < 8; nf++)
#pragma unroll
                    for (int j = 0; j < 4; j++) acc[mi][nf][j] = 0.f;
        }

        const uint32_t bbuf = b_base + (uint32_t)(bt % NBUF) * BT_BYTES;
#pragma unroll
        for (int s = 0; s < 4; s++) {
            uint32_t a0[4], a1[4];
            uint32_t cA = (uint32_t)(ktl * 8 + s * 2) + cbaseA;
            uint32_t aaddr = a_lane + ((cA ^ swzA) << 4);
            ldsm_x4(a0, aaddr);
            ldsm_x4(a1, aaddr + 16384u);
            uint32_t b[4][4];
            uint32_t cB = ((uint32_t)(s * 2) + kh) ^ swzB;
#pragma unroll
            for (int p = 0; p < 4; p++)
                ldsm_x4(b[p], bbuf + rowoffB[p] + (cB << 4));
#pragma unroll
            for (int p = 0; p < 4; p++) {
                mma_bf16(acc[0][2 * p],     a0, b[p][0], b[p][1]);
                mma_bf16(acc[0][2 * p + 1], a0, b[p][2], b[p][3]);
                mma_bf16(acc[1][2 * p],     a1, b[p][0], b[p][1]);
                mma_bf16(acc[1][2 * p + 1], a1, b[p][2], b[p][3]);
            }
        }

        if (ktl == 7) {
            const int nc = bt >> 3;
            const int vbase = nc * 256 + warp_n * 64 + (lane & 3) * 2;
#pragma unroll
            for (int g = 0; g < 4; g++) {
                const int mi = g >> 1, hf = (g & 1) * 2;
                float ls = 0.f;
#pragma unroll
                for (int nf = 0; nf < 8; nf++)
                    ls += __expf(acc[mi][nf][hf]) + __expf(acc[mi][nf][hf + 1]);
                ls += __shfl_xor_sync(FM, ls, 1);
                ls += __shfl_xor_sync(FM, ls, 2);
                sm[g] += ls;
#pragma unroll
                for (int nf = 0; nf < 8; nf++) {
                    int v0 = vbase + nf * 8;
                    if (v0 == 0)         blankv[g] = acc[mi][nf][hf];
                    if (v0 == tg[g])     tgtv[g]   = acc[mi][nf][hf];
                    if (v0 + 1 == tg[g]) tgtv[g]   = acc[mi][nf][hf + 1];
                }
            }
        }
    }

    // gather captured values across the 4 lanes of each row group
#pragma unroll
    for (int g = 0; g < 4; g++) {
        tgtv[g]   += __shfl_xor_sync(FM, tgtv[g], 1);
        tgtv[g]   += __shfl_xor_sync(FM, tgtv[g], 2);
        blankv[g] += __shfl_xor_sync(FM, blankv[g], 1);
        blankv[g] += __shfl_xor_sync(FM, blankv[g], 2);
    }

    // reuse B buffer smem for the cross-n-warp combine
    __syncthreads();
    float* ssum   = reinterpret_cast<float*>(dyn) + ((b_base - smem_u32(dyn)) >> 2);
    float* stgtv  = ssum + 4 * MTILE;
    float* sblank = stgtv + 4 * MTILE;

    if ((lane & 3) == 0) {
#pragma unroll
        for (int g = 0; g < 4; g++) {
            int m = warp_m * 32 + (g >> 1) * 16 + (g & 1) * 8 + (lane >> 2);
            ssum[warp_n * MTILE + m]  = sm[g];
            stgtv[warp_n * MTILE + m] = tgtv[g];
            if (warp_n == 0) sblank[m] = blankv[g];
        }
    }
    __syncthreads();

    if (tid < MTILE) {
        int m = tid;
        float lse = __logf(ssum[m] + ssum[MTILE + m] + ssum[2 * MTILE + m] + ssum[3 * MTILE + m]);
        int g = g0 + m;
        int b = g / (TT * UP);
        int r = g - b * (TT * UP);
        int t = r / UP, u = r - t * UP;
        g_blank[g] = sblank[m] - lse;
        if (u < UU) {
            int h = (tgtm[m] >> 6) & 3;   // which 64-col N-warp owns target
            g_emit[(size_t)(b * TT + t) * UU + u] = stgtv[h * MTILE + m] - lse;
        }
    }
}

// =====================================================================
// K4: alpha DP — anti-diagonal wavefront with smem-staged operands.
// 256 threads: all warps cooperatively stage blank/emit, warp 0 runs DP.
// =====================================================================
__device__ __forceinline__ float lse2(float a, float b) {
    float m = fmaxf(a, b);
    float n = fminf(a, b);
    return m + __logf(1.f + __expf(n - m));
}

#define DP_BL_FLOATS (TT*UP)   // 16640
#define DP_EM_FLOATS (TT*UU)   // 16384
#define DP_SMEM_BYTES ((DP_BL_FLOATS + DP_EM_FLOATS) * 4)   // 132096

__global__ void __launch_bounds__(256, 1) dp_kernel(
    const int* __restrict__ in_len, const int* __restrict__ tgt_len)
{
    extern __shared__ float sdp[];
    float* sbl = sdp;                   // [TT*UP]
    float* sem = sdp + DP_BL_FLOATS;    // [TT*UU]

    const int b = blockIdx.x;
    const int tid = threadIdx.x;

    // ---- stage blank/emit into smem (float4, coalesced) ----
    {
        const float4* gb = reinterpret_cast<const float4*>(g_blank + (size_t)b * DP_BL_FLOATS);
        float4* sb = reinterpret_cast<float4*>(sbl);
#pragma unroll
        for (int i = 0; i < DP_BL_FLOATS / 4 / 256 + 1; i++) {
            int q = tid + i * 256;
            if (q < DP_BL_FLOATS / 4) sb[q] = gb[q];
        }
        const float4* ge = reinterpret_cast<const float4*>(g_emit + (size_t)b * DP_EM_FLOATS);
        float4* se = reinterpret_cast<float4*>(sem);
#pragma unroll
        for (int i = 0; i < DP_EM_FLOATS / 4 / 256; i++) {
            int q = tid + i * 256;
            se[q] = ge[q];
        }
    }
    __syncthreads();

    if (tid >= 32) return;
    const int lane = tid;
    const int til = in_len[b];
    const int ul  = tgt_len[b];
    const int dmax = til - 1 + ul;
    const float NEG = -1e30f;
    const unsigned FM = 0xffffffffu;

    int u[3];
    float al[3];
    bool uok[3];
#pragma unroll
    for (int j = 0; j < 3; j++) {
        u[j] = lane * 3 + j;
        uok[j] = (u[j] <= UU);
        al[j] = (u[j] == 0) ? 0.f : NEG;
    }

    // operands for step d=1
    float bl[3], em[3];
#pragma unroll
    for (int j = 0; j < 3; j++) {
        int t = 1 - u[j];
        bl[j] = (t >= 1 && uok[j]) ? sbl[(t - 1) * UP + u[j]] : 0.f;
        em[j] = (t >= 0 && u[j] >= 1 && uok[j]) ? sem[t * UU + u[j] - 1] : 0.f;
    }

    float fin = NEG;

#pragma unroll 1
    for (int d = 1; d <= dmax; d++) {
        // prefetch next step's operands from smem
        float nbl[3], nem[3];
        if (d < dmax) {
#pragma unroll
            for (int j = 0; j < 3; j++) {
                int t = d + 1 - u[j];
                nbl[j] = (t >= 1 && t <= TT && uok[j]) ? sbl[(t - 1) * UP + u[j]] : 0.f;
                nem[j] = (t >= 0 && t < TT && u[j] >= 1 && uok[j]) ? sem[t * UU + u[j] - 1] : 0.f;
            }
        }

        float nb0 = __shfl_up_sync(FM, al[2], 1);
        if (lane == 0) nb0 = NEG;

        float nw[3];
        nw[0] = lse2(al[0] + bl[0], nb0   + em[0]);
        nw[1] = lse2(al[1] + bl[1], al[0] + em[1]);
        nw[2] = lse2(al[2] + bl[2], al[1] + em[2]);

#pragma unroll
        for (int j = 0; j < 3; j++) {
            int t = d - u[j];
            if (t < 0 || t >= TT || !uok[j]) nw[j] = NEG;
            al[j] = nw[j];
            if (d == dmax && u[j] == ul) fin = nw[j];
        }

        bl[0] = nbl[0]; bl[1] = nbl[1]; bl[2] = nbl[2];
        em[0] = nem[0]; em[1] = nem[1]; em[2] = nem[2];
    }

#pragma unroll
    for (int j = 0; j < 3; j++) {
        if (u[j] == ul) g_final[b] = fin + sbl[(til - 1) * UP + ul];
    }
}

__global__ void finalize_kernel(float* out) {
    out[0] = -0.25f * (g_final[0] + g_final[1] + g_final[2] + g_final[3]);
}

// =====================================================================
// launch
// =====================================================================
extern "C" void kernel_launch(void* const* d_in, const int* in_sizes, int n_in,
                              void* d_out, int out_size)
{
    const float* enc     = (const float*)d_in[0];
    const float* dec     = (const float*)d_in[1];
    const int*   targets = (const int*)  d_in[2];
    const int*   in_len  = (const int*)  d_in[3];
    const int*   tgt_len = (const int*)  d_in[4];
    const float* W_enc   = (const float*)d_in[5];
    const float* b_enc   = (const float*)d_in[6];
    const float* W_dec   = (const float*)d_in[7];
    const float* b_dec   = (const float*)d_in[8];
    const float* W_proj  = (const float*)d_in[9];

    void *pe = nullptr, *pd = nullptr;
    cudaGetSymbolAddress(&pe, g_enc_h);
    cudaGetSymbolAddress(&pd, g_dec_h);

    const int smem_joint = 1024 + A_BYTES + NBUF * BT_BYTES;   // 230400 B
    cudaFuncSetAttribute(joint_kernel, cudaFuncAttributeMaxDynamicSharedMemorySize, smem_joint);
    cudaFuncSetAttribute(dp_kernel, cudaFuncAttributeMaxDynamicSharedMemorySize, DP_SMEM_BYTES);

    convert_wp_kernel<<<(VV * DJ) / 256, 256>>>(W_proj);

    dim3 gg((BB * TT + 63) / 64, DJ / 64, 2);
    gemm_bias_kernel<<<gg, 256>>>(enc, W_enc, b_enc, (float*)pe, BB * TT,
                                  dec, W_dec, b_dec, (float*)pd, BB * UP);

    joint_kernel<<<(BB * TT * UP) / MTILE, JTHREADS, smem_joint>>>(targets);

    dp_kernel<<<BB, 256, DP_SMEM_BYTES>>>(in_len, tgt_len);

    finalize_kernel<<<1, 1>>>((float*)d_out);
}